// round 13
// baseline (speedup 1.0000x reference)
#include <cuda_runtime.h>
#include <cuda_fp16.h>
#include <cstdint>

// 3-term fp16-split GEMM, all operands "entity-major": row = m or n entity,
// cols = kwords (word packs logical k and k+8 of its k16 block).
// D = Ah*Bh + Al*Bh + Ah*Bl via mma.sync m16n8k16; fragments via ldmatrix.x4.

#define RS 12                     // words per smem row (8 data + 4 pad)
#define TILE_W (128 * RS)         // 1536 words per tile (one operand plane)
#define STG_B 24576               // bytes per stage (4 tiles)
#define SMEM_BYTES (3 * STG_B)    // 73728

// tag: 0 eUt, 1 eUcat, 2 eHx, 3 eHa, 4 eHb, 5 eAGG, 6 eM1, 7 eM2T, 8 eW1, 9 eW2
__device__ uint32_t eUt  [2u * 1572864u];   // [pl][z][i][512]   (k = j)
__device__ uint32_t eUcat[2u * 1572864u];   // [pl][i][1536]     (k = z*1024+j)
__device__ uint32_t eHx  [2u * 2097152u];   // [pl][b*64+d][512] (k = j)
__device__ uint32_t eHa  [2u * 4194304u];   // [pl][b*128+d][512]
__device__ uint32_t eHb  [2u * 4194304u];
__device__ uint32_t eAGG [2u * 12582912u];  // [pl][z][b*1024+i][Din/2]
__device__ uint32_t eM1  [2u * 12582912u];  // [pl][z][b*1024+i][64]
__device__ uint32_t eM2T [2u * 12582912u];  // [pl][b*128+o][1536] (k = z*1024+i)
__device__ uint32_t eW1  [2u * 24576u];     // [pl][z][h][Din/2]
__device__ uint32_t eW2  [2u * 24576u];     // [pl][z][o][64]
__device__ float    g_pooled[8192];

__device__ __forceinline__ uint32_t* resolve(int t) {
    switch (t) {
        case 0: return eUt;  case 1: return eUcat; case 2: return eHx;
        case 3: return eHa;  case 4: return eHb;   case 5: return eAGG;
        case 6: return eM1;  case 7: return eM2T;  case 8: return eW1;
        default: return eW2;
    }
}

__device__ __forceinline__ void hsplit(float v, uint32_t& h, uint32_t& l) {
    const __half hh = __float2half_rn(v);
    const __half ll = __float2half_rn(v - __half2float(hh));
    h = (uint32_t)__half_as_ushort(hh);
    l = (uint32_t)__half_as_ushort(ll);
}
__device__ __forceinline__ uint32_t pck(uint32_t a, uint32_t b) { return a | (b << 16); }

#define CP16(dst, src) \
    asm volatile("cp.async.cg.shared.global [%0], [%1], 16;" :: "r"(dst), "l"(src))
#define CP_COMMIT() asm volatile("cp.async.commit_group;")
#define CP_WAIT1()  asm volatile("cp.async.wait_group 1;")

#define LDSM4(r0, r1, r2, r3, a)                                              \
    asm volatile("ldmatrix.sync.aligned.m8n8.x4.shared.b16 {%0,%1,%2,%3}, [%4];" \
        : "=r"(r0), "=r"(r1), "=r"(r2), "=r"(r3) : "r"(a))

#define MMA16(d, a, b0, b1)                                                   \
    asm volatile(                                                             \
        "mma.sync.aligned.m16n8k16.row.col.f32.f16.f16.f32 "                  \
        "{%0,%1,%2,%3},{%4,%5,%6,%7},{%8,%9},{%0,%1,%2,%3};"                  \
        : "+f"(d[0]), "+f"(d[1]), "+f"(d[2]), "+f"(d[3])                      \
        : "r"(a[0]), "r"(a[1]), "r"(a[2]), "r"(a[3]), "r"(b0), "r"(b1))

// ---------------------------------------------------------------------------
__global__ void __launch_bounds__(256, 2)
gemmL(int aTag, long long aZ, long long aPl, int ldaW,
      int bTag, long long bZ, long long bPl, int ldbW,
      int oTag, long long oZ, long long oPl, int ldoW, int outMode, int lgD,
      int K,
      const float* __restrict__ bias, int biasZ,
      const float* __restrict__ bwPtr, int reluFlag)
{
    extern __shared__ uint32_t smw[];
    const uint32_t sbase = (uint32_t)__cvta_generic_to_shared(smw);

    const int z = blockIdx.z, bx = blockIdx.x, by = blockIdx.y;
    const uint32_t* A = resolve(aTag) + (long long)z * aZ + (size_t)by * 128 * ldaW;
    const uint32_t* B = resolve(bTag) + (long long)z * bZ + (size_t)bx * 128 * ldbW;
    if (bias) bias += (size_t)z * biasZ;

    const int tid = threadIdx.x, warp = tid >> 5, lane = tid & 31;
    const int warpM = (warp >> 2) * 64, warpN = (warp & 3) * 32;
    const int c4 = lane & 3, g = lane >> 2;

    // ldmatrix per-lane word offsets (within a tile)
    const int lane7 = lane & 7;
    const int aOff = (warpM + lane7 + ((lane >> 3) & 1) * 8) * RS + ((lane >> 4) & 1) * 4;
    const int bOff = (warpN + lane7 + ((lane >> 4) & 1) * 8) * RS + ((lane >> 3) & 1) * 4;

    float acc[4][4][4];
#pragma unroll
    for (int i = 0; i < 4; i++)
#pragma unroll
        for (int j = 0; j < 4; j++)
#pragma unroll
            for (int r = 0; r < 4; r++) acc[i][j][r] = 0.f;

    // loader: 1024 CP16s / 256 threads = 4 each (tiles: Ah, Al, Bh, Bl)
    auto issue_stage = [&](int s) {
        const int st = s % 3;
#pragma unroll
        for (int q = 0; q < 4; q++) {
            const int idx = tid + q * 256;
            const int tile = idx >> 8;           // q == tile here (256 per tile)
            const int row = (idx >> 1) & 127;
            const int half = idx & 1;
            const uint32_t* src;
            if (tile == 0)      src = A + (size_t)row * ldaW;
            else if (tile == 1) src = A + aPl + (size_t)row * ldaW;
            else if (tile == 2) src = B + (size_t)row * ldbW;
            else                src = B + bPl + (size_t)row * ldbW;
            src += s * 8 + half * 4;
            CP16(sbase + st * STG_B + tile * 6144 + (row * RS + half * 4) * 4, src);
        }
        CP_COMMIT();
    };

    const int NS = K >> 4;
    issue_stage(0);
    issue_stage(1);

    for (int s = 0; s < NS; s++) {
        const int st = s % 3;
        CP_WAIT1();
        __syncthreads();
        if (s + 2 < NS) issue_stage(s + 2);
        else            CP_COMMIT();

        const uint32_t stb = sbase + st * STG_B;
        uint32_t bh[4][2], bl[4][2];
#pragma unroll
        for (int jp = 0; jp < 2; jp++) {
            const uint32_t bb = stb + (bOff + jp * 16 * RS) * 4;
            LDSM4(bh[2 * jp][0], bh[2 * jp][1], bh[2 * jp + 1][0], bh[2 * jp + 1][1],
                  bb + 12288);
            LDSM4(bl[2 * jp][0], bl[2 * jp][1], bl[2 * jp + 1][0], bl[2 * jp + 1][1],
                  bb + 18432);
        }
#pragma unroll
        for (int it = 0; it < 4; it++) {
            const uint32_t aa = stb + (aOff + it * 16 * RS) * 4;
            uint32_t ah[4], al[4];
            LDSM4(ah[0], ah[1], ah[2], ah[3], aa);
            LDSM4(al[0], al[1], al[2], al[3], aa + 6144);
#pragma unroll
            for (int j = 0; j < 4; j++) {
                MMA16(acc[it][j], ah, bh[j][0], bh[j][1]);
                MMA16(acc[it][j], al, bh[j][0], bh[j][1]);
                MMA16(acc[it][j], ah, bl[j][0], bl[j][1]);
            }
        }
        __syncthreads();
    }

    float alpha = 1.f;
    if (bwPtr) {
        const float w0 = bwPtr[0], w1 = bwPtr[1], w2 = bwPtr[2];
        const float mx = fmaxf(w0, fmaxf(w1, w2));
        const float e0 = expf(w0 - mx), e1 = expf(w1 - mx), e2 = expf(w2 - mx);
        alpha = (z == 0 ? e0 : (z == 1 ? e1 : e2)) / (e0 + e1 + e2);
    }

    uint32_t* OH = resolve(oTag) + (long long)z * oZ;
    uint32_t* OL = OH + oPl;

    auto post = [&](float v, int n) -> float {
        if (bias) v += bias[n];
        v *= alpha;
        if (reluFlag) v = fmaxf(v, 0.f);
        return v;
    };

    if (outMode <= 1) {
        // A-role output: word packs cols (n, n+8)
        const int Dmask = (1 << lgD) - 1;
#pragma unroll
        for (int it = 0; it < 4; it++) {
#pragma unroll
            for (int half = 0; half < 2; half++) {
                const int m0 = by * 128 + warpM + it * 16 + g + 8 * half;
#pragma unroll
                for (int jp = 0; jp < 2; jp++) {
                    uint32_t wh[2], wl[2];
                    int n0 = 0;
#pragma unroll
                    for (int ss = 0; ss < 2; ss++) {
                        const int nL = warpN + jp * 16 + 2 * c4 + ss;
                        const int nG = bx * 128 + nL;
                        if (ss == 0) n0 = nG;
                        const float v0 = post(acc[it][2 * jp][half * 2 + ss], nL);
                        const float v1 = post(acc[it][2 * jp + 1][half * 2 + ss], nL + 8);
                        uint32_t h0, l0, h1, l1;
                        hsplit(v0, h0, l0);
                        hsplit(v1, h1, l1);
                        wh[ss] = pck(h0, h1);
                        wl[ss] = pck(l0, l1);
                    }
                    size_t row, wc;
                    if (outMode == 0) {
                        row = (size_t)m0;
                        wc = ((n0 >> 4) << 3) + (n0 & 7);
                    } else {
                        const int d = n0 & Dmask;
                        row = (size_t)((n0 >> lgD) << 10) + m0;
                        wc = ((d >> 4) << 3) + (d & 7);
                    }
                    const size_t ad = row * ldoW + wc;
                    *reinterpret_cast<uint2*>(OH + ad) = make_uint2(wh[0], wh[1]);
                    *reinterpret_cast<uint2*>(OL + ad) = make_uint2(wl[0], wl[1]);
                }
            }
        }
    } else {
        // B-role output: word packs rows (m, m+8)
#pragma unroll
        for (int it = 0; it < 4; it++) {
            const int m0 = by * 128 + warpM + it * 16 + g;
            const int mi = m0 & 1023;
            const size_t wc = ((mi >> 4) << 3) + (mi & 7);
            const size_t rowB = (size_t)((m0 >> 10) << 7);
#pragma unroll
            for (int j = 0; j < 4; j++) {
#pragma unroll
                for (int ss = 0; ss < 2; ss++) {
                    const int nL = warpN + j * 8 + 2 * c4 + ss;
                    const int nG = bx * 128 + nL;
                    const float v0 = post(acc[it][j][ss], nL);
                    const float v1 = post(acc[it][j][2 + ss], nL);
                    uint32_t h0, l0, h1, l1;
                    hsplit(v0, h0, l0);
                    hsplit(v1, h1, l1);
                    const size_t ad = (rowB + nG) * ldoW + wc;
                    OH[ad] = pck(h0, h1);
                    OL[ad] = pck(l0, l1);
                }
            }
        }
    }
}

// ---------------- prep kernels ----------------
__global__ void prep_Ut(const float* __restrict__ U)
{
    const int idx = blockIdx.x * 256 + threadIdx.x;   // 1572864
    const int zz = idx >> 19, rem = idx & 524287, i = rem >> 9, w = rem & 511;
    const int jlo = ((w >> 3) << 4) + (w & 7);
    uint32_t h0, l0, h1, l1;
    hsplit(U[((size_t)zz << 20) + ((size_t)jlo << 10) + i], h0, l0);
    hsplit(U[((size_t)zz << 20) + ((size_t)(jlo + 8) << 10) + i], h1, l1);
    eUt[idx] = pck(h0, h1);
    eUt[1572864u + idx] = pck(l0, l1);
}
__global__ void prep_Ucat(const float* __restrict__ U)
{
    const int idx = blockIdx.x * 256 + threadIdx.x;   // 1572864
    const int i = idx / 1536, w = idx % 1536;
    const int klo = ((w >> 3) << 4) + (w & 7);
    const int zz = klo >> 10, j = klo & 1023;
    uint32_t h0, l0, h1, l1;
    hsplit(U[((size_t)zz << 20) + ((size_t)i << 10) + j], h0, l0);
    hsplit(U[((size_t)zz << 20) + ((size_t)i << 10) + j + 8], h1, l1);
    eUcat[idx] = pck(h0, h1);
    eUcat[1572864u + idx] = pck(l0, l1);
}
__global__ void prep_x(const float* __restrict__ x)
{
    const int idx = blockIdx.x * 256 + threadIdx.x;   // 2097152
    const int row = idx >> 9, w = idx & 511;
    const int jlo = ((w >> 3) << 4) + (w & 7);
    const int b = row >> 6, d = row & 63;
    uint32_t h0, l0, h1, l1;
    hsplit(x[((size_t)b << 16) + ((size_t)jlo << 6) + d], h0, l0);
    hsplit(x[((size_t)b << 16) + ((size_t)(jlo + 8) << 6) + d], h1, l1);
    eHx[idx] = pck(h0, h1);
    eHx[2097152u + idx] = pck(l0, l1);
}
__global__ void prep_w(const float* __restrict__ w1, int Din,
                       const float* __restrict__ w2)
{
    const int idx = blockIdx.x * 256 + threadIdx.x;   // 24576
    const int rows1 = Din >> 1;
    if (idx < 3 * 128 * rows1) {
        const int zz = idx / (128 * rows1), rem = idx - zz * 128 * rows1;
        const int h = rem / rows1, w = rem - h * rows1;
        const int dlo = ((w >> 3) << 4) + (w & 7);
        uint32_t h0, l0, h1, l1;
        hsplit(w1[(size_t)zz * Din * 128 + (size_t)dlo * 128 + h], h0, l0);
        hsplit(w1[(size_t)zz * Din * 128 + (size_t)(dlo + 8) * 128 + h], h1, l1);
        eW1[zz * 128 * rows1 + h * rows1 + w] = pck(h0, h1);
        eW1[24576u + zz * 128 * rows1 + h * rows1 + w] = pck(l0, l1);
    }
    {
        const int zz = idx >> 13, rem = idx & 8191, o = rem >> 6, w = rem & 63;
        const int hlo = ((w >> 3) << 4) + (w & 7);
        uint32_t h0, l0, h1, l1;
        hsplit(w2[(size_t)zz * 16384 + (size_t)hlo * 128 + o], h0, l0);
        hsplit(w2[(size_t)zz * 16384 + (size_t)(hlo + 8) * 128 + o], h1, l1);
        eW2[idx] = pck(h0, h1);
        eW2[24576u + idx] = pck(l0, l1);
    }
}

__global__ void pool_kernel(int srcTag)
{
    const uint32_t* H = resolve(srcTag);
    const uint32_t* L = H + 4194304u;
    const int row = blockIdx.x * 8 + (threadIdx.x >> 5), lane = threadIdx.x & 31;
    float s = 0.f;
    for (int w = lane; w < 512; w += 32) {
        const uint32_t wh = H[(size_t)row * 512 + w], wl = L[(size_t)row * 512 + w];
        s += __half2float(__ushort_as_half((unsigned short)(wh & 0xFFFF)))
           + __half2float(__ushort_as_half((unsigned short)(wh >> 16)))
           + __half2float(__ushort_as_half((unsigned short)(wl & 0xFFFF)))
           + __half2float(__ushort_as_half((unsigned short)(wl >> 16)));
    }
    for (int o = 16; o; o >>= 1) s += __shfl_xor_sync(0xFFFFFFFFu, s, o);
    if (lane == 0) g_pooled[row] = s * (1.f / 1024.f);
}

__global__ void classifier_kernel(const float* __restrict__ Wc1,
                                  const float* __restrict__ bc1,
                                  const float* __restrict__ al,
                                  const float* __restrict__ Wc2,
                                  const float* __restrict__ bc2,
                                  float* __restrict__ out)
{
    __shared__ float zs[64][128];
    const int t = threadIdx.x;
    for (int idx = t; idx < 64 * 128; idx += 256) {
        const int b = idx >> 7, h = idx & 127;
        float acc = bc1[h];
        for (int d = 0; d < 128; d++)
            acc = fmaf(g_pooled[b * 128 + d], Wc1[d * 128 + h], acc);
        zs[b][h] = acc > 0.f ? acc : al[h] * acc;
    }
    __syncthreads();
    const int b = t >> 2, c = t & 3;
    float acc = bc2[c];
    for (int h = 0; h < 128; h++)
        acc = fmaf(zs[b][h], Wc2[h * 4 + c], acc);
    out[b * 4 + c] = acc;
}

// ---------------------------------------------------------------------------
extern "C" void kernel_launch(void* const* d_in, const int* in_sizes, int n_in,
                              void* d_out, int out_size)
{
    const float* x    = (const float*)d_in[0];
    const float* U    = (const float*)d_in[1];
    const float* w1_0 = (const float*)d_in[2];
    const float* b1_0 = (const float*)d_in[3];
    const float* w2_0 = (const float*)d_in[4];
    const float* b2_0 = (const float*)d_in[5];
    const float* w1_r = (const float*)d_in[6];
    const float* b1_r = (const float*)d_in[7];
    const float* w2_r = (const float*)d_in[8];
    const float* b2_r = (const float*)d_in[9];
    const float* bw   = (const float*)d_in[10];
    const float* Wc1  = (const float*)d_in[11];
    const float* bc1  = (const float*)d_in[12];
    const float* alp  = (const float*)d_in[13];
    const float* Wc2  = (const float*)d_in[14];
    const float* bc2  = (const float*)d_in[15];
    float* out = (float*)d_out;

    cudaFuncSetAttribute(gemmL, cudaFuncAttributeMaxDynamicSharedMemorySize, SMEM_BYTES);

    prep_Ut<<<6144, 256>>>(U);
    prep_Ucat<<<6144, 256>>>(U);
    prep_x<<<8192, 256>>>(x);

    int hinTag = 2, houtTag = 3;   // l0 in eHx; outs eHa, eHb, eHa
    for (int l = 0; l < 3; l++) {
        const int Din = (l == 0) ? 64 : 128;
        const int lgD = (l == 0) ? 6 : 7;
        const int rows1 = Din >> 1;
        const float* w1 = (l == 0) ? w1_0 : (w1_r + (size_t)(l - 1) * 3 * 128 * 128);
        const float* b1 = (l == 0) ? b1_0 : (b1_r + (size_t)(l - 1) * 3 * 128);
        const float* w2 = (l == 0) ? w2_0 : (w2_r + (size_t)(l - 1) * 3 * 128 * 128);
        const float* b2 = (l == 0) ? b2_0 : (b2_r + (size_t)(l - 1) * 3 * 128);
        const long long hPl = (l == 0) ? 2097152LL : 4194304LL;
        const long long AGGz = 65536LL * rows1;

        prep_w<<<96, 256>>>(w1, Din, w2);

        // G1: AGG[z][(b<<10)+i][kw(d)] = sum_j Ut[z][i][.] * H[b*D+d][.]
        gemmL<<<dim3(64 * Din / 128, 8, 3), 256, SMEM_BYTES>>>(
            0, 524288LL, 1572864LL, 512,
            hinTag, 0LL, hPl, 512,
            5, AGGz, 12582912LL, rows1, 1, lgD,
            1024, nullptr, 0, nullptr, 0);
        // G2: M1[z][m'][kw(h)] = relu(sum_d AGG[z][m'][.] * W1[z][h][.] + b1)
        gemmL<<<dim3(1, 512, 3), 256, SMEM_BYTES>>>(
            5, AGGz, 12582912LL, rows1,
            8, 128LL * rows1, 24576LL, rows1,
            6, 4194304LL, 12582912LL, 64, 0, lgD,
            Din, b1, 128, nullptr, 1);
        // G3: M2T[(m'>>10)*128+o][kw(z*1024 + m'&1023)] = ws_z*(M1 @ W2 + b2)
        gemmL<<<dim3(1, 512, 3), 256, SMEM_BYTES>>>(
            6, 4194304LL, 12582912LL, 64,
            9, 8192LL, 24576LL, 64,
            7, 512LL, 12582912LL, 1536, 2, 7,
            128, b2, 128, bw + l * 3, 0);
        // G4: H_out[c][kw(i)] = relu(sum_kp Ucat[i][.] * M2T[c][.])
        gemmL<<<dim3(64, 8, 1), 256, SMEM_BYTES>>>(
            1, 0LL, 1572864LL, 1536,
            7, 0LL, 12582912LL, 1536,
            houtTag, 0LL, 4194304LL, 512, 2, 7,
            3072, nullptr, 0, nullptr, 1);

        hinTag = houtTag;
        houtTag = (houtTag == 3) ? 4 : 3;
    }

    pool_kernel<<<1024, 256>>>(hinTag);   // final H in eHa (tag 3)
    classifier_kernel<<<1, 256>>>(Wc1, bc1, alp, Wc2, bc2, out);
}

// round 14
// speedup vs baseline: 1.0247x; 1.0247x over previous
#include <cuda_runtime.h>
#include <cuda_fp16.h>
#include <cstdint>

// 3-term fp16-split GEMM (round-11 design) + persistent CTAs.
// Word packs logical ks (k, k+8) of its k16 block.
// D = Ah*Bh + Al*Bh + Ah*Bl. A: m-major 2-plane. B: k-word-row 2-plane.

#define A_RS 12
#define B_RS 136
#define STG_W (2 * 128 * A_RS + 2 * 8 * B_RS)   // 5248 words
#define SMEM_BYTES (3 * STG_W * 4)               // 62976
#define NPERS 296                                 // 2 CTAs/SM x 148 SMs

// A-role: [plane0|plane1], rows m, K/2 words/row
__device__ uint32_t eUt  [2u * 1572864u];   // [z][i][512]  zs=524288
__device__ uint32_t eUcat[2u * 1572864u];   // [i][1536]
__device__ uint32_t eAGG [2u * 12582912u];  // zs=4194304 ([b*1024+i][Din/2])
__device__ uint32_t eM1  [2u * 12582912u];  // [m'][64]
// B-role: word rows kp=(k>>4)*8+(k&7), cols n
__device__ uint32_t eM2  [2u * 12582912u];  // [1536][8192]
__device__ uint32_t eHx  [2u * 2097152u];   // [512][4096]
__device__ uint32_t eHa  [2u * 4194304u];   // [512][8192]
__device__ uint32_t eHb  [2u * 4194304u];
__device__ uint32_t eW1  [2u * 24576u];     // [z][64][128] zs=8192
__device__ uint32_t eW2  [2u * 24576u];
__device__ float    g_pooled[8192];

__device__ __forceinline__ uint32_t* resolve(int t) {
    switch (t) {
        case 0: return eUt;  case 1: return eUcat; case 2: return eAGG;
        case 3: return eM1;  case 4: return eM2;   case 5: return eHx;
        case 6: return eHa;  case 7: return eHb;   case 8: return eW1;
        default: return eW2;
    }
}

__device__ __forceinline__ void hsplit(float v, uint32_t& h, uint32_t& l) {
    const __half hh = __float2half_rn(v);
    const __half ll = __float2half_rn(v - __half2float(hh));
    h = (uint32_t)__half_as_ushort(hh);
    l = (uint32_t)__half_as_ushort(ll);
}
__device__ __forceinline__ uint32_t pck(uint32_t a, uint32_t b) { return a | (b << 16); }

__device__ __forceinline__ uint32_t sm2u(const void* p) {
    return (uint32_t)__cvta_generic_to_shared(p);
}
#define CP16(dst, src) \
    asm volatile("cp.async.cg.shared.global [%0], [%1], 16;" :: "r"(dst), "l"(src))
#define CP_COMMIT() asm volatile("cp.async.commit_group;")
#define CP_WAIT1()  asm volatile("cp.async.wait_group 1;")

#define MMA16(d, a, b0, b1)                                                   \
    asm volatile(                                                             \
        "mma.sync.aligned.m16n8k16.row.col.f32.f16.f16.f32 "                  \
        "{%0,%1,%2,%3},{%4,%5,%6,%7},{%8,%9},{%0,%1,%2,%3};"                  \
        : "+f"(d[0]), "+f"(d[1]), "+f"(d[2]), "+f"(d[3])                      \
        : "r"(a[0]), "r"(a[1]), "r"(a[2]), "r"(a[3]), "r"(b0), "r"(b1))

// ---------------------------------------------------------------------------
__global__ void __launch_bounds__(256, 2)
gemmP(int tilesX, int tilesY, int tilesZ,
      int aTag, long long aZ, long long aP, int ldaW,
      int bTag, long long bZ, long long bP, int ldbW,
      int oTag, long long oZ, long long oP, int ldoW, int outMode, int Din,
      int K, const float* __restrict__ biasBase, int biasZ,
      const float* __restrict__ bwPtr, int reluFlag)
{
    extern __shared__ uint32_t smw[];

    const int tid = threadIdx.x, warp = tid >> 5, lane = tid & 31;
    const int warpM = (warp >> 2) * 64, warpN = (warp & 3) * 32;
    const int c4 = lane & 3, g = lane >> 2;

    const int ar = tid >> 1, ahw = (tid & 1) * 4;       // A loader
    const int br = tid >> 5, bc = (tid & 31) * 4;       // B loader
    const int NS = K >> 4;
    const int numTiles = tilesX * tilesY * tilesZ;

    const uint32_t* A;
    const uint32_t* B;

    auto issue_stage = [&](int s, int st) {
        const int base = st * STG_W;
        const uint32_t* srcA = A + (size_t)ar * ldaW + s * 8 + ahw;
        CP16(sm2u(smw + base + ar * A_RS + ahw), srcA);
        CP16(sm2u(smw + base + 1536 + ar * A_RS + ahw), srcA + aP);
        const uint32_t* srcB = B + (size_t)(s * 8 + br) * ldbW + bc;
        CP16(sm2u(smw + base + 3072 + br * B_RS + bc), srcB);
        CP16(sm2u(smw + base + 4160 + br * B_RS + bc), srcB + bP);
        CP_COMMIT();
    };

    for (int t = blockIdx.x; t < numTiles; t += NPERS) {
        const int bx = t % tilesX;
        const int by = (t / tilesX) % tilesY;
        const int z  = t / (tilesX * tilesY);

        A = resolve(aTag) + (long long)z * aZ + (size_t)(by * 128) * ldaW;
        B = resolve(bTag) + (long long)z * bZ + bx * 128;
        const float* bias = biasBase ? (biasBase + (size_t)z * biasZ) : nullptr;

        float acc[4][4][4];
#pragma unroll
        for (int i = 0; i < 4; i++)
#pragma unroll
            for (int j = 0; j < 4; j++)
#pragma unroll
                for (int r = 0; r < 4; r++) acc[i][j][r] = 0.f;

        __syncthreads();                    // prev tile fully consumed
        issue_stage(0, 0);
        issue_stage(1, 1);

        for (int s = 0; s < NS; s++) {
            const int cur = s % 3;
            CP_WAIT1();
            __syncthreads();
            if (s + 2 < NS) issue_stage(s + 2, (s + 2) % 3);
            else            CP_COMMIT();

            const int base = cur * STG_W;
            uint32_t bh[4][2], bl[4][2];
#pragma unroll
            for (int j = 0; j < 4; j++) {
                const int n = warpN + j * 8 + g;
                bh[j][0] = smw[base + 3072 + c4 * B_RS + n];
                bh[j][1] = smw[base + 3072 + (c4 + 4) * B_RS + n];
                bl[j][0] = smw[base + 4160 + c4 * B_RS + n];
                bl[j][1] = smw[base + 4160 + (c4 + 4) * B_RS + n];
            }
#pragma unroll
            for (int it = 0; it < 4; it++) {
                const int m = warpM + it * 16 + g;
                const int ab = base + m * A_RS;
                uint32_t ah[4], al[4];
                ah[0] = smw[ab + c4];                 ah[1] = smw[ab + 8 * A_RS + c4];
                ah[2] = smw[ab + c4 + 4];             ah[3] = smw[ab + 8 * A_RS + c4 + 4];
                al[0] = smw[ab + 1536 + c4];          al[1] = smw[ab + 1536 + 8 * A_RS + c4];
                al[2] = smw[ab + 1536 + c4 + 4];      al[3] = smw[ab + 1536 + 8 * A_RS + c4 + 4];
#pragma unroll
                for (int j = 0; j < 4; j++) {
                    MMA16(acc[it][j], ah, bh[j][0], bh[j][1]);
                    MMA16(acc[it][j], al, bh[j][0], bh[j][1]);
                    MMA16(acc[it][j], ah, bl[j][0], bl[j][1]);
                }
            }
        }

        float alpha = 1.f;
        if (bwPtr) {
            const float w0 = bwPtr[0], w1 = bwPtr[1], w2 = bwPtr[2];
            const float mx = fmaxf(w0, fmaxf(w1, w2));
            const float e0 = expf(w0 - mx), e1 = expf(w1 - mx), e2 = expf(w2 - mx);
            alpha = (z == 0 ? e0 : (z == 1 ? e1 : e2)) / (e0 + e1 + e2);
        }

        uint32_t* OH = resolve(oTag) + (long long)z * oZ;
        uint32_t* OL = OH + oP;

        auto post = [&](float v, int n) -> float {
            if (bias) v += bias[n];
            v *= alpha;
            if (reluFlag) v = fmaxf(v, 0.f);
            return v;
        };

        if (outMode == 0 || outMode == 3) {
            // A-role output: word packs cols (n, n+8)
#pragma unroll
            for (int it = 0; it < 4; it++) {
#pragma unroll
                for (int half = 0; half < 2; half++) {
                    const int row = by * 128 + warpM + it * 16 + g + 8 * half;
#pragma unroll
                    for (int jp = 0; jp < 2; jp++) {
                        uint32_t wh[2], wl[2];
                        int n0 = 0;
#pragma unroll
                        for (int ss = 0; ss < 2; ss++) {
                            const int n = bx * 128 + warpN + 16 * jp + 2 * c4 + ss;
                            if (ss == 0) n0 = n;
                            const float v0 = post(acc[it][2 * jp][half * 2 + ss], n);
                            const float v1 = post(acc[it][2 * jp + 1][half * 2 + ss], n + 8);
                            uint32_t h0, l0, h1, l1;
                            hsplit(v0, h0, l0);
                            hsplit(v1, h1, l1);
                            wh[ss] = pck(h0, h1);
                            wl[ss] = pck(l0, l1);
                        }
                        size_t ad;
                        if (outMode == 0) {
                            ad = (size_t)row * ldoW + (n0 >> 4) * 8 + (n0 & 7);
                        } else {
                            const int bb = n0 / Din, dr = n0 % Din;
                            ad = (size_t)bb * (1024 * (Din / 2)) + (size_t)row * (Din / 2)
                               + (dr >> 4) * 8 + (dr & 7);
                        }
                        *reinterpret_cast<uint2*>(OH + ad) = make_uint2(wh[0], wh[1]);
                        *reinterpret_cast<uint2*>(OL + ad) = make_uint2(wl[0], wl[1]);
                    }
                }
            }
        } else {
            // B-role output: word packs rows (k, k+8)
#pragma unroll
            for (int it = 0; it < 4; it++) {
                const int r0 = by * 128 + warpM + it * 16 + g;
                const int kk = (outMode == 1) ? r0 : z * 1024 + (r0 & 1023);
                const int wr = (kk >> 4) * 8 + (kk & 7);
                const int bb = r0 >> 10;
#pragma unroll
                for (int j = 0; j < 4; j++) {
                    uint32_t wh[2], wl[2];
                    int nc0 = 0;
#pragma unroll
                    for (int ss = 0; ss < 2; ss++) {
                        const int n = warpN + j * 8 + 2 * c4 + ss;
                        const int nc = (outMode == 1) ? bx * 128 + n : bb * 128 + n;
                        if (ss == 0) nc0 = nc;
                        const float v0 = post(acc[it][j][ss], n);
                        const float v1 = post(acc[it][j][2 + ss], n);
                        uint32_t h0, l0, h1, l1;
                        hsplit(v0, h0, l0);
                        hsplit(v1, h1, l1);
                        wh[ss] = pck(h0, h1);
                        wl[ss] = pck(l0, l1);
                    }
                    const size_t ad = (size_t)wr * ldoW + nc0;
                    *reinterpret_cast<uint2*>(OH + ad) = make_uint2(wh[0], wh[1]);
                    *reinterpret_cast<uint2*>(OL + ad) = make_uint2(wl[0], wl[1]);
                }
            }
        }
    }
}

// ---------------- prep kernels (identical to round 11) ----------------
__global__ void prep_Ut(const float* __restrict__ U)
{
    const int idx = blockIdx.x * 256 + threadIdx.x;   // 1572864
    const int z = idx >> 19, rem = idx & 524287, i = rem >> 9, w = rem & 511;
    const int jlo = ((w >> 3) << 4) + (w & 7);
    uint32_t h0, l0, h1, l1;
    hsplit(U[((size_t)z << 20) + ((size_t)jlo << 10) + i], h0, l0);
    hsplit(U[((size_t)z << 20) + ((size_t)(jlo + 8) << 10) + i], h1, l1);
    eUt[idx] = pck(h0, h1);
    eUt[1572864u + idx] = pck(l0, l1);
}
__global__ void prep_Ucat(const float* __restrict__ U)
{
    const int idx = blockIdx.x * 256 + threadIdx.x;   // 1572864
    const int i = idx / 1536, w = idx % 1536;
    const int klo = ((w >> 3) << 4) + (w & 7);
    const int z = klo >> 10, j = klo & 1023;
    uint32_t h0, l0, h1, l1;
    hsplit(U[((size_t)z << 20) + ((size_t)i << 10) + j], h0, l0);
    hsplit(U[((size_t)z << 20) + ((size_t)i << 10) + j + 8], h1, l1);
    eUcat[idx] = pck(h0, h1);
    eUcat[1572864u + idx] = pck(l0, l1);
}
__global__ void prep_x(const float* __restrict__ x)
{
    const int idx = blockIdx.x * 256 + threadIdx.x;   // 2097152
    const int kp = idx >> 12, n = idx & 4095;
    const int jlo = ((kp >> 3) << 4) + (kp & 7);
    const int b = n >> 6, d = n & 63;
    uint32_t h0, l0, h1, l1;
    hsplit(x[((size_t)b << 16) + ((size_t)jlo << 6) + d], h0, l0);
    hsplit(x[((size_t)b << 16) + ((size_t)(jlo + 8) << 6) + d], h1, l1);
    eHx[idx] = pck(h0, h1);
    eHx[2097152u + idx] = pck(l0, l1);
}
__global__ void prep_w(const float* __restrict__ w1, int Din,
                       const float* __restrict__ w2)
{
    const int idx = blockIdx.x * 256 + threadIdx.x;   // 24576
    const int rows1 = Din / 2;
    if (idx < 3 * rows1 * 128) {
        const int z = idx / (rows1 * 128), wr = (idx / 128) % rows1, h = idx % 128;
        const int dlo = ((wr >> 3) << 4) + (wr & 7);
        uint32_t h0, l0, h1, l1;
        hsplit(w1[(size_t)z * Din * 128 + (size_t)dlo * 128 + h], h0, l0);
        hsplit(w1[(size_t)z * Din * 128 + (size_t)(dlo + 8) * 128 + h], h1, l1);
        eW1[z * 8192 + wr * 128 + h] = pck(h0, h1);
        eW1[24576u + z * 8192 + wr * 128 + h] = pck(l0, l1);
    }
    {
        const int z = idx / 8192, wr = (idx / 128) % 64, h = idx % 128;
        const int dlo = ((wr >> 3) << 4) + (wr & 7);
        uint32_t h0, l0, h1, l1;
        hsplit(w2[(size_t)z * 16384 + (size_t)dlo * 128 + h], h0, l0);
        hsplit(w2[(size_t)z * 16384 + (size_t)(dlo + 8) * 128 + h], h1, l1);
        eW2[idx] = pck(h0, h1);
        eW2[24576u + idx] = pck(l0, l1);
    }
}

__global__ void pool_kernel()
{
    const int b = blockIdx.x, t = threadIdx.x;
    const int d = t & 127, s4 = t >> 7;
    float sum = 0.f;
    for (int wr = s4; wr < 512; wr += 4) {
        const size_t off = (size_t)wr * 8192 + b * 128 + d;
        const uint32_t wh = eHa[off], wl = eHa[4194304u + off];
        sum += __half2float(__ushort_as_half((unsigned short)(wh & 0xFFFF)))
             + __half2float(__ushort_as_half((unsigned short)(wh >> 16)))
             + __half2float(__ushort_as_half((unsigned short)(wl & 0xFFFF)))
             + __half2float(__ushort_as_half((unsigned short)(wl >> 16)));
    }
    __shared__ float red[512];
    red[t] = sum;
    __syncthreads();
    if (s4 == 0)
        g_pooled[b * 128 + d] =
            (red[d] + red[d + 128] + red[d + 256] + red[d + 384]) * (1.f / 1024.f);
}

__global__ void classifier_kernel(const float* __restrict__ Wc1,
                                  const float* __restrict__ bc1,
                                  const float* __restrict__ al,
                                  const float* __restrict__ Wc2,
                                  const float* __restrict__ bc2,
                                  float* __restrict__ out)
{
    __shared__ float zs[64][128];
    const int t = threadIdx.x;
    for (int idx = t; idx < 64 * 128; idx += 256) {
        const int b = idx >> 7, h = idx & 127;
        float acc = bc1[h];
        for (int d = 0; d < 128; d++)
            acc = fmaf(g_pooled[b * 128 + d], Wc1[d * 128 + h], acc);
        zs[b][h] = acc > 0.f ? acc : al[h] * acc;
    }
    __syncthreads();
    const int b = t >> 2, c = t & 3;
    float acc = bc2[c];
    for (int h = 0; h < 128; h++)
        acc = fmaf(zs[b][h], Wc2[h * 4 + c], acc);
    out[b * 4 + c] = acc;
}

// ---------------------------------------------------------------------------
extern "C" void kernel_launch(void* const* d_in, const int* in_sizes, int n_in,
                              void* d_out, int out_size)
{
    const float* x    = (const float*)d_in[0];
    const float* U    = (const float*)d_in[1];
    const float* w1_0 = (const float*)d_in[2];
    const float* b1_0 = (const float*)d_in[3];
    const float* w2_0 = (const float*)d_in[4];
    const float* b2_0 = (const float*)d_in[5];
    const float* w1_r = (const float*)d_in[6];
    const float* b1_r = (const float*)d_in[7];
    const float* w2_r = (const float*)d_in[8];
    const float* b2_r = (const float*)d_in[9];
    const float* bw   = (const float*)d_in[10];
    const float* Wc1  = (const float*)d_in[11];
    const float* bc1  = (const float*)d_in[12];
    const float* alp  = (const float*)d_in[13];
    const float* Wc2  = (const float*)d_in[14];
    const float* bc2  = (const float*)d_in[15];
    float* out = (float*)d_out;

    cudaFuncSetAttribute(gemmP, cudaFuncAttributeMaxDynamicSharedMemorySize, SMEM_BYTES);

    prep_Ut<<<6144, 256>>>(U);
    prep_Ucat<<<6144, 256>>>(U);
    prep_x<<<8192, 256>>>(x);

    int hinTag = 5, houtTag = 6;   // l0 in: eHx; outs: eHa, eHb, eHa
    for (int l = 0; l < 3; l++) {
        const int Din   = (l == 0) ? 64 : 128;
        const int Wcols = 64 * Din;
        const float* w1 = (l == 0) ? w1_0 : (w1_r + (size_t)(l - 1) * 3 * 128 * 128);
        const float* b1 = (l == 0) ? b1_0 : (b1_r + (size_t)(l - 1) * 3 * 128);
        const float* w2 = (l == 0) ? w2_0 : (w2_r + (size_t)(l - 1) * 3 * 128 * 128);
        const float* b2 = (l == 0) ? b2_0 : (b2_r + (size_t)(l - 1) * 3 * 128);
        const long long hP  = (l == 0) ? 2097152LL : 4194304LL;
        const int       hLd = (l == 0) ? 4096 : 8192;

        prep_w<<<96, 256>>>(w1, Din, w2);

        // G1: AGG_z = U_z^T @ H  (mode3 -> eAGG b-major flat)
        gemmP<<<NPERS, 256, SMEM_BYTES>>>(
            Wcols / 128, 8, 3,
            0, 524288LL, 1572864LL, 512,
            hinTag, 0LL, hP, hLd,
            2, 4194304LL, 12582912LL, 0, 3, Din,
            1024, nullptr, 0, nullptr, 0);
        // G2: M1_z = relu(AGG_z @ w1_z + b1_z)  (mode0 -> eM1)
        gemmP<<<NPERS, 256, SMEM_BYTES>>>(
            1, 512, 3,
            2, 4194304LL, 12582912LL, Din / 2,
            8, 8192LL, 24576LL, 128,
            3, 4194304LL, 12582912LL, 64, 0, 0,
            Din, b1, 128, nullptr, 1);
        // G3: M2_z = ws_z*(M1_z @ w2_z + b2_z)  (mode2 -> eM2)
        gemmP<<<NPERS, 256, SMEM_BYTES>>>(
            1, 512, 3,
            3, 4194304LL, 12582912LL, 64,
            9, 8192LL, 24576LL, 128,
            4, 0LL, 12582912LL, 8192, 2, 0,
            128, b2, 128, bw + l * 3, 0);
        // G4: H_out = relu(Ucat @ M2_all)  (mode1 -> eH)
        gemmP<<<NPERS, 256, SMEM_BYTES>>>(
            64, 8, 1,
            1, 0LL, 1572864LL, 1536,
            4, 0LL, 12582912LL, 8192,
            houtTag, 0LL, 4194304LL, 8192, 1, 0,
            3072, nullptr, 0, nullptr, 1);

        hinTag = houtTag;
        houtTag = (houtTag == 6) ? 7 : 6;
    }

    pool_kernel<<<64, 512>>>();
    classifier_kernel<<<1, 256>>>(Wc1, bc1, alp, Wc2, bc2, out);
}

// round 15
// speedup vs baseline: 1.0823x; 1.0561x over previous
#include <cuda_runtime.h>
#include <cuda_fp16.h>
#include <cstdint>

// 3-term fp16-split GEMM (round-11 design).
// Changes vs r11: inner MMAs reordered term-major (breaks acc RAW chains),
// single barrier per stage, weight prep hoisted to one upfront launch.

#define A_RS 12
#define B_RS 136
#define STG_W (2 * 128 * A_RS + 2 * 8 * B_RS)   // 5248 words
#define SMEM_BYTES (3 * STG_W * 4)               // 62976

// A-role: [plane0|plane1], rows m, K/2 words/row
__device__ uint32_t eUt  [2u * 1572864u];   // [z][i][512]  zs=524288
__device__ uint32_t eUcat[2u * 1572864u];   // [i][1536]
__device__ uint32_t eAGG [2u * 12582912u];  // zs=4194304 ([b*1024+i][Din/2])
__device__ uint32_t eM1  [2u * 12582912u];  // [m'][64]
// B-role: word rows kp=(k>>4)*8+(k&7), cols n
__device__ uint32_t eM2  [2u * 12582912u];  // [1536][8192]
__device__ uint32_t eHx  [2u * 2097152u];   // [512][4096]
__device__ uint32_t eHa  [2u * 4194304u];   // [512][8192]
__device__ uint32_t eHb  [2u * 4194304u];
__device__ uint32_t eW1  [2u * 73728u];     // [layer][z][64][128], layer slab 24576
__device__ uint32_t eW2  [2u * 73728u];
__device__ float    g_pooled[8192];

__device__ __forceinline__ uint32_t* resolve(int t) {
    switch (t) {
        case 0: return eUt;  case 1: return eUcat; case 2: return eAGG;
        case 3: return eM1;  case 4: return eM2;   case 5: return eHx;
        case 6: return eHa;  case 7: return eHb;   case 8: return eW1;
        default: return eW2;
    }
}

__device__ __forceinline__ void hsplit(float v, uint32_t& h, uint32_t& l) {
    const __half hh = __float2half_rn(v);
    const __half ll = __float2half_rn(v - __half2float(hh));
    h = (uint32_t)__half_as_ushort(hh);
    l = (uint32_t)__half_as_ushort(ll);
}
__device__ __forceinline__ uint32_t pck(uint32_t a, uint32_t b) { return a | (b << 16); }

__device__ __forceinline__ uint32_t sm2u(const void* p) {
    return (uint32_t)__cvta_generic_to_shared(p);
}
#define CP16(dst, src) \
    asm volatile("cp.async.cg.shared.global [%0], [%1], 16;" :: "r"(dst), "l"(src))
#define CP_COMMIT() asm volatile("cp.async.commit_group;")
#define CP_WAIT1()  asm volatile("cp.async.wait_group 1;")

#define MMA16(d, a, b0, b1)                                                   \
    asm volatile(                                                             \
        "mma.sync.aligned.m16n8k16.row.col.f32.f16.f16.f32 "                  \
        "{%0,%1,%2,%3},{%4,%5,%6,%7},{%8,%9},{%0,%1,%2,%3};"                  \
        : "+f"(d[0]), "+f"(d[1]), "+f"(d[2]), "+f"(d[3])                      \
        : "r"(a[0]), "r"(a[1]), "r"(a[2]), "r"(a[3]), "r"(b0), "r"(b1))

// ---------------------------------------------------------------------------
__global__ void __launch_bounds__(256, 2)
gemm3(int aTag, long long aZ, long long aP, int ldaW,
      int bTag, long long bZ, long long bP, int ldbW, long long bBase,
      int oTag, long long oZ, long long oP, int ldoW, int outMode, int Din,
      int K, const float* __restrict__ bias, int biasZ,
      const float* __restrict__ bwPtr, int reluFlag)
{
    extern __shared__ uint32_t smw[];
    const int z = blockIdx.z, bx = blockIdx.x, by = blockIdx.y;
    const uint32_t* A = resolve(aTag) + (long long)z * aZ;
    const uint32_t* B = resolve(bTag) + (long long)z * bZ + bBase;
    if (bias) bias += (size_t)z * biasZ;

    const int tid = threadIdx.x, warp = tid >> 5, lane = tid & 31;
    const int warpM = (warp >> 2) * 64, warpN = (warp & 3) * 32;
    const int c4 = lane & 3, g = lane >> 2;

    float acc[4][4][4];
#pragma unroll
    for (int i = 0; i < 4; i++)
#pragma unroll
        for (int j = 0; j < 4; j++)
#pragma unroll
            for (int r = 0; r < 4; r++) acc[i][j][r] = 0.f;

    const int ar = tid >> 1, ahw = (tid & 1) * 4;       // A loader
    const int br = tid >> 5, bc = (tid & 31) * 4;       // B loader

    auto issue_stage = [&](int s, int st) {
        const int base = st * STG_W;
        const uint32_t* srcA = A + (size_t)(by * 128 + ar) * ldaW + s * 8 + ahw;
        CP16(sm2u(smw + base + ar * A_RS + ahw), srcA);
        CP16(sm2u(smw + base + 1536 + ar * A_RS + ahw), srcA + aP);
        const uint32_t* srcB = B + (size_t)(s * 8 + br) * ldbW + bx * 128 + bc;
        CP16(sm2u(smw + base + 3072 + br * B_RS + bc), srcB);
        CP16(sm2u(smw + base + 4160 + br * B_RS + bc), srcB + bP);
        CP_COMMIT();
    };

    const int NS = K >> 4;
    issue_stage(0, 0);
    issue_stage(1, 1);

    for (int s = 0; s < NS; s++) {
        const int cur = s % 3;
        CP_WAIT1();
        __syncthreads();            // single barrier per stage: protects slot reuse
        if (s + 2 < NS) issue_stage(s + 2, (s + 2) % 3);
        else            CP_COMMIT();

        const int base = cur * STG_W;
        uint32_t bh[4][2], bl[4][2];
#pragma unroll
        for (int j = 0; j < 4; j++) {
            const int n = warpN + j * 8 + g;
            bh[j][0] = smw[base + 3072 + c4 * B_RS + n];
            bh[j][1] = smw[base + 3072 + (c4 + 4) * B_RS + n];
            bl[j][0] = smw[base + 4160 + c4 * B_RS + n];
            bl[j][1] = smw[base + 4160 + (c4 + 4) * B_RS + n];
        }
#pragma unroll
        for (int it = 0; it < 4; it++) {
            const int m = warpM + it * 16 + g;
            const int ab = base + m * A_RS;
            uint32_t ah[4], al[4];
            ah[0] = smw[ab + c4];                 ah[1] = smw[ab + 8 * A_RS + c4];
            ah[2] = smw[ab + c4 + 4];             ah[3] = smw[ab + 8 * A_RS + c4 + 4];
            al[0] = smw[ab + 1536 + c4];          al[1] = smw[ab + 1536 + 8 * A_RS + c4];
            al[2] = smw[ab + 1536 + c4 + 4];      al[3] = smw[ab + 1536 + 8 * A_RS + c4 + 4];
            // term-major order: same-acc MMAs spaced 4 apart (no RAW stall)
#pragma unroll
            for (int j = 0; j < 4; j++) MMA16(acc[it][j], ah, bh[j][0], bh[j][1]);
#pragma unroll
            for (int j = 0; j < 4; j++) MMA16(acc[it][j], al, bh[j][0], bh[j][1]);
#pragma unroll
            for (int j = 0; j < 4; j++) MMA16(acc[it][j], ah, bl[j][0], bl[j][1]);
        }
    }

    float alpha = 1.f;
    if (bwPtr) {
        const float w0 = bwPtr[0], w1 = bwPtr[1], w2 = bwPtr[2];
        const float mx = fmaxf(w0, fmaxf(w1, w2));
        const float e0 = expf(w0 - mx), e1 = expf(w1 - mx), e2 = expf(w2 - mx);
        alpha = (z == 0 ? e0 : (z == 1 ? e1 : e2)) / (e0 + e1 + e2);
    }

    uint32_t* OH = resolve(oTag) + (long long)z * oZ;
    uint32_t* OL = OH + oP;

    auto post = [&](float v, int n) -> float {
        if (bias) v += bias[n];
        v *= alpha;
        if (reluFlag) v = fmaxf(v, 0.f);
        return v;
    };

    if (outMode == 0 || outMode == 3) {
        // A-role output: word packs cols (n, n+8)
#pragma unroll
        for (int it = 0; it < 4; it++) {
#pragma unroll
            for (int half = 0; half < 2; half++) {
                const int row = by * 128 + warpM + it * 16 + g + 8 * half;
#pragma unroll
                for (int jp = 0; jp < 2; jp++) {
                    uint32_t wh[2], wl[2];
                    int n0 = 0;
#pragma unroll
                    for (int ss = 0; ss < 2; ss++) {
                        const int n = bx * 128 + warpN + 16 * jp + 2 * c4 + ss;
                        if (ss == 0) n0 = n;
                        const float v0 = post(acc[it][2 * jp][half * 2 + ss], n);
                        const float v1 = post(acc[it][2 * jp + 1][half * 2 + ss], n + 8);
                        uint32_t h0, l0, h1, l1;
                        hsplit(v0, h0, l0);
                        hsplit(v1, h1, l1);
                        wh[ss] = pck(h0, h1);
                        wl[ss] = pck(l0, l1);
                    }
                    size_t ad;
                    if (outMode == 0) {
                        ad = (size_t)row * ldoW + (n0 >> 4) * 8 + (n0 & 7);
                    } else {
                        const int bb = n0 / Din, dr = n0 % Din;
                        ad = (size_t)bb * (1024 * (Din / 2)) + (size_t)row * (Din / 2)
                           + (dr >> 4) * 8 + (dr & 7);
                    }
                    *reinterpret_cast<uint2*>(OH + ad) = make_uint2(wh[0], wh[1]);
                    *reinterpret_cast<uint2*>(OL + ad) = make_uint2(wl[0], wl[1]);
                }
            }
        }
    } else {
        // B-role output: word packs rows (k, k+8)
#pragma unroll
        for (int it = 0; it < 4; it++) {
            const int r0 = by * 128 + warpM + it * 16 + g;
            const int kk = (outMode == 1) ? r0 : z * 1024 + (r0 & 1023);
            const int wr = (kk >> 4) * 8 + (kk & 7);
            const int bb = r0 >> 10;
#pragma unroll
            for (int j = 0; j < 4; j++) {
                uint32_t wh[2], wl[2];
                int nc0 = 0;
#pragma unroll
                for (int ss = 0; ss < 2; ss++) {
                    const int n = warpN + j * 8 + 2 * c4 + ss;
                    const int nc = (outMode == 1) ? bx * 128 + n : bb * 128 + n;
                    if (ss == 0) nc0 = nc;
                    const float v0 = post(acc[it][j][ss], n);
                    const float v1 = post(acc[it][j][2 + ss], n);
                    uint32_t h0, l0, h1, l1;
                    hsplit(v0, h0, l0);
                    hsplit(v1, h1, l1);
                    wh[ss] = pck(h0, h1);
                    wl[ss] = pck(l0, l1);
                }
                const size_t ad = (size_t)wr * ldoW + nc0;
                *reinterpret_cast<uint2*>(OH + ad) = make_uint2(wh[0], wh[1]);
                *reinterpret_cast<uint2*>(OL + ad) = make_uint2(wl[0], wl[1]);
            }
        }
    }
}

// ---------------- prep kernels ----------------
__global__ void prep_Ut(const float* __restrict__ U)
{
    const int idx = blockIdx.x * 256 + threadIdx.x;   // 1572864
    const int z = idx >> 19, rem = idx & 524287, i = rem >> 9, w = rem & 511;
    const int jlo = ((w >> 3) << 4) + (w & 7);
    uint32_t h0, l0, h1, l1;
    hsplit(U[((size_t)z << 20) + ((size_t)jlo << 10) + i], h0, l0);
    hsplit(U[((size_t)z << 20) + ((size_t)(jlo + 8) << 10) + i], h1, l1);
    eUt[idx] = pck(h0, h1);
    eUt[1572864u + idx] = pck(l0, l1);
}
__global__ void prep_Ucat(const float* __restrict__ U)
{
    const int idx = blockIdx.x * 256 + threadIdx.x;   // 1572864
    const int i = idx / 1536, w = idx % 1536;
    const int klo = ((w >> 3) << 4) + (w & 7);
    const int z = klo >> 10, j = klo & 1023;
    uint32_t h0, l0, h1, l1;
    hsplit(U[((size_t)z << 20) + ((size_t)i << 10) + j], h0, l0);
    hsplit(U[((size_t)z << 20) + ((size_t)i << 10) + j + 8], h1, l1);
    eUcat[idx] = pck(h0, h1);
    eUcat[1572864u + idx] = pck(l0, l1);
}
__global__ void prep_x(const float* __restrict__ x)
{
    const int idx = blockIdx.x * 256 + threadIdx.x;   // 2097152
    const int kp = idx >> 12, n = idx & 4095;
    const int jlo = ((kp >> 3) << 4) + (kp & 7);
    const int b = n >> 6, d = n & 63;
    uint32_t h0, l0, h1, l1;
    hsplit(x[((size_t)b << 16) + ((size_t)jlo << 6) + d], h0, l0);
    hsplit(x[((size_t)b << 16) + ((size_t)(jlo + 8) << 6) + d], h1, l1);
    eHx[idx] = pck(h0, h1);
    eHx[2097152u + idx] = pck(l0, l1);
}
// All layers' weights in one launch. Layer slab = 24576 words/plane.
__global__ void prep_w_all(const float* __restrict__ w1_0,
                           const float* __restrict__ w1_r,
                           const float* __restrict__ w2_0,
                           const float* __restrict__ w2_r)
{
    const int idx = blockIdx.x * 256 + threadIdx.x;   // 73728
    const int l = idx / 24576, rem = idx % 24576;
    const int z = rem >> 13, r2 = rem & 8191, wr = r2 >> 7, h = r2 & 127;
    const int dlo = ((wr >> 3) << 4) + (wr & 7);
    {   // w2: [3][128][128], rows kp over h (64 rows), cols o
        const float* w2 = (l == 0) ? w2_0 : (w2_r + (size_t)(l - 1) * 3 * 16384);
        uint32_t h0, l0, h1, l1;
        hsplit(w2[(size_t)z * 16384 + (size_t)dlo * 128 + h], h0, l0);
        hsplit(w2[(size_t)z * 16384 + (size_t)(dlo + 8) * 128 + h], h1, l1);
        eW2[idx] = pck(h0, h1);
        eW2[73728u + idx] = pck(l0, l1);
    }
    {   // w1: rows kp over d (Din/2 rows), cols h
        const int Din = (l == 0) ? 64 : 128;
        if (wr < (Din >> 1)) {
            const float* w1 = (l == 0) ? w1_0 : (w1_r + (size_t)(l - 1) * 3 * 128 * 128);
            uint32_t h0, l0, h1, l1;
            hsplit(w1[(size_t)z * Din * 128 + (size_t)dlo * 128 + h], h0, l0);
            hsplit(w1[(size_t)z * Din * 128 + (size_t)(dlo + 8) * 128 + h], h1, l1);
            eW1[idx] = pck(h0, h1);
            eW1[73728u + idx] = pck(l0, l1);
        }
    }
}

__global__ void pool_kernel()
{
    const int b = blockIdx.x, t = threadIdx.x;
    const int d = t & 127, s4 = t >> 7;
    float sum = 0.f;
    for (int wr = s4; wr < 512; wr += 4) {
        const size_t off = (size_t)wr * 8192 + b * 128 + d;
        const uint32_t wh = eHa[off], wl = eHa[4194304u + off];
        sum += __half2float(__ushort_as_half((unsigned short)(wh & 0xFFFF)))
             + __half2float(__ushort_as_half((unsigned short)(wh >> 16)))
             + __half2float(__ushort_as_half((unsigned short)(wl & 0xFFFF)))
             + __half2float(__ushort_as_half((unsigned short)(wl >> 16)));
    }
    __shared__ float red[512];
    red[t] = sum;
    __syncthreads();
    if (s4 == 0)
        g_pooled[b * 128 + d] =
            (red[d] + red[d + 128] + red[d + 256] + red[d + 384]) * (1.f / 1024.f);
}

__global__ void classifier_kernel(const float* __restrict__ Wc1,
                                  const float* __restrict__ bc1,
                                  const float* __restrict__ al,
                                  const float* __restrict__ Wc2,
                                  const float* __restrict__ bc2,
                                  float* __restrict__ out)
{
    __shared__ float zs[64][128];
    const int t = threadIdx.x;
    for (int idx = t; idx < 64 * 128; idx += 256) {
        const int b = idx >> 7, h = idx & 127;
        float acc = bc1[h];
        for (int d = 0; d < 128; d++)
            acc = fmaf(g_pooled[b * 128 + d], Wc1[d * 128 + h], acc);
        zs[b][h] = acc > 0.f ? acc : al[h] * acc;
    }
    __syncthreads();
    const int b = t >> 2, c = t & 3;
    float acc = bc2[c];
    for (int h = 0; h < 128; h++)
        acc = fmaf(zs[b][h], Wc2[h * 4 + c], acc);
    out[b * 4 + c] = acc;
}

// ---------------------------------------------------------------------------
extern "C" void kernel_launch(void* const* d_in, const int* in_sizes, int n_in,
                              void* d_out, int out_size)
{
    const float* x    = (const float*)d_in[0];
    const float* U    = (const float*)d_in[1];
    const float* w1_0 = (const float*)d_in[2];
    const float* b1_0 = (const float*)d_in[3];
    const float* w2_0 = (const float*)d_in[4];
    const float* b2_0 = (const float*)d_in[5];
    const float* w1_r = (const float*)d_in[6];
    const float* b1_r = (const float*)d_in[7];
    const float* w2_r = (const float*)d_in[8];
    const float* b2_r = (const float*)d_in[9];
    const float* bw   = (const float*)d_in[10];
    const float* Wc1  = (const float*)d_in[11];
    const float* bc1  = (const float*)d_in[12];
    const float* alp  = (const float*)d_in[13];
    const float* Wc2  = (const float*)d_in[14];
    const float* bc2  = (const float*)d_in[15];
    float* out = (float*)d_out;

    cudaFuncSetAttribute(gemm3, cudaFuncAttributeMaxDynamicSharedMemorySize, SMEM_BYTES);

    prep_Ut<<<6144, 256>>>(U);
    prep_Ucat<<<6144, 256>>>(U);
    prep_x<<<8192, 256>>>(x);
    prep_w_all<<<288, 256>>>(w1_0, w1_r, w2_0, w2_r);

    int hinTag = 5, houtTag = 6;   // l0 in: eHx; outs: eHa, eHb, eHa
    for (int l = 0; l < 3; l++) {
        const int Din   = (l == 0) ? 64 : 128;
        const int Wcols = 64 * Din;
        const float* b1 = (l == 0) ? b1_0 : (b1_r + (size_t)(l - 1) * 3 * 128);
        const float* b2 = (l == 0) ? b2_0 : (b2_r + (size_t)(l - 1) * 3 * 128);
        const long long hP  = (l == 0) ? 2097152LL : 4194304LL;
        const int       hLd = (l == 0) ? 4096 : 8192;
        const long long wBase = (long long)l * 24576;

        // G1: AGG_z = U_z^T @ H  (mode3 -> eAGG b-major flat)
        gemm3<<<dim3(Wcols / 128, 8, 3), 256, SMEM_BYTES>>>(
            0, 524288LL, 1572864LL, 512,
            hinTag, 0LL, hP, hLd, 0LL,
            2, 4194304LL, 12582912LL, 0, 3, Din,
            1024, nullptr, 0, nullptr, 0);
        // G2: M1_z = relu(AGG_z @ w1_z + b1_z)  (mode0 -> eM1)
        gemm3<<<dim3(1, 512, 3), 256, SMEM_BYTES>>>(
            2, 4194304LL, 12582912LL, Din / 2,
            8, 8192LL, 73728LL, 128, wBase,
            3, 4194304LL, 12582912LL, 64, 0, 0,
            Din, b1, 128, nullptr, 1);
        // G3: M2_z = ws_z*(M1_z @ w2_z + b2_z)  (mode2 -> eM2)
        gemm3<<<dim3(1, 512, 3), 256, SMEM_BYTES>>>(
            3, 4194304LL, 12582912LL, 64,
            9, 8192LL, 73728LL, 128, wBase,
            4, 0LL, 12582912LL, 8192, 2, 0,
            128, b2, 128, bw + l * 3, 0);
        // G4: H_out = relu(Ucat @ M2_all)  (mode1 -> eH)
        gemm3<<<dim3(64, 8, 1), 256, SMEM_BYTES>>>(
            1, 0LL, 1572864LL, 1536,
            4, 0LL, 12582912LL, 8192, 0LL,
            houtTag, 0LL, 4194304LL, 8192, 1, 0,
            3072, nullptr, 0, nullptr, 1);

        hinTag = houtTag;
        houtTag = (houtTag == 6) ? 7 : 6;
    }

    pool_kernel<<<64, 512>>>();
    classifier_kernel<<<1, 256>>>(Wc1, bc1, alp, Wc2, bc2, out);
}